// round 1
// baseline (speedup 1.0000x reference)
#include <cuda_runtime.h>
#include <math.h>

// Total elements of the [32,96,56,56] tensor
#define NTOT 9633792            // 32*96*3136
#define BATCH_STRIDE 301056     // 96*3136
#define CHUNK 18816             // 24*784 per cluster-batch (512 chunks)

// Scratch (device globals; no allocation allowed)
__device__ float g_V[NTOT];
__device__ float g_F[NTOT];
__device__ float g_H[NTOT];
__device__ float g_O[NTOT];

// ---------------------------------------------------------------------------
// conv1x1 as GEMM: Y[b, co, s] = bias[co] + sum_k W[co,k] * X[b, k, s]
// Block tile: all 96 co x 128 spatial positions, one batch. 256 threads,
// each computes 12 co x 4 s. Weights staged k-major in smem (broadcast f4).
// ---------------------------------------------------------------------------
__global__ void __launch_bounds__(256) conv_gemm(
    const float* __restrict__ X, const float* __restrict__ W,
    const float* __restrict__ bias, float* __restrict__ Y)
{
    extern __shared__ float sm[];
    float* Xs = sm;              // [96][128]
    float* Ws = sm + 96 * 128;   // [96][100]  k-major, padded row

    const int b   = blockIdx.y;
    const int s0  = blockIdx.x * 128;
    const int tid = threadIdx.x;

    for (int i = tid; i < 96 * 96; i += 256) {
        int o = i / 96, k = i - o * 96;
        Ws[k * 100 + o] = W[i];
    }
    const float* Xb = X + (size_t)b * BATCH_STRIDE;
    for (int i = tid; i < 96 * 128; i += 256) {
        int k = i >> 7, j = i & 127;
        int s = s0 + j;
        Xs[i] = (s < 3136) ? Xb[k * 3136 + s] : 0.0f;
    }
    __syncthreads();

    const int j0  = (tid & 31) * 4;
    const int co0 = (tid >> 5) * 12;

    float acc[12][4];
    #pragma unroll
    for (int c = 0; c < 12; c++)
        #pragma unroll
        for (int j = 0; j < 4; j++) acc[c][j] = 0.0f;

    #pragma unroll 4
    for (int k = 0; k < 96; k++) {
        float4 xv = *(const float4*)&Xs[k * 128 + j0];
        float4 w0 = *(const float4*)&Ws[k * 100 + co0];
        float4 w1 = *(const float4*)&Ws[k * 100 + co0 + 4];
        float4 w2 = *(const float4*)&Ws[k * 100 + co0 + 8];
        float wv[12] = {w0.x, w0.y, w0.z, w0.w,
                        w1.x, w1.y, w1.z, w1.w,
                        w2.x, w2.y, w2.z, w2.w};
        float xj[4] = {xv.x, xv.y, xv.z, xv.w};
        #pragma unroll
        for (int c = 0; c < 12; c++)
            #pragma unroll
            for (int j = 0; j < 4; j++)
                acc[c][j] = fmaf(wv[c], xj[j], acc[c][j]);
    }

    if (s0 + j0 < 3136) {   // 3136 % 4 == 0 so full float4 is valid
        #pragma unroll
        for (int c = 0; c < 12; c++) {
            int co = co0 + c;
            float bv = bias[co];
            float4 r = make_float4(acc[c][0] + bv, acc[c][1] + bv,
                                   acc[c][2] + bv, acc[c][3] + bv);
            *(float4*)&Y[(size_t)b * BATCH_STRIDE + co * 3136 + s0 + j0] = r;
        }
    }
}

// ---------------------------------------------------------------------------
// Clustering kernel: one block per cluster-batch B (512 total).
// All the reference reshapes are flat, so chunk B is buf[B*18816 .. +18816):
//   windowed [c2][28][28] view:      idx = c2*784 + s'
//   token    [n][ch]      view:      idx = n*24 + ch
// ---------------------------------------------------------------------------
__global__ void __launch_bounds__(256) cluster_kernel(
    const float* __restrict__ Vg, const float* __restrict__ Fg,
    const float* __restrict__ Hg,
    const float* __restrict__ Wc, const float* __restrict__ bc,
    const float* __restrict__ alphap, const float* __restrict__ betap,
    float* __restrict__ Og)
{
    const int B   = blockIdx.x;
    const int tid = threadIdx.x;
    const float* Vw = Vg + (size_t)B * CHUNK;
    const float* Fw = Fg + (size_t)B * CHUNK;
    const float* Hw = Hg + (size_t)B * CHUNK;
    float*       Ow = Og + (size_t)B * CHUNK;

    __shared__ float sPoolH[96];     // chw-flat: c2*4 + pos
    __shared__ float sPoolF[96];
    __shared__ float sC1[96];        // [m*24+ch] centers after Wc conv
    __shared__ float sC2[96];        // [m*24+ch] centers after sim0 @ feature
    __shared__ float sOutC[96];      // [m*24+ch]
    __shared__ float sPart[96][2];
    __shared__ float sCN[4][24];     // normalized cn
    __shared__ float sNorm[4];
    __shared__ float sSim0[4][784];
    __shared__ float sSimVal[784];
    __shared__ int   sAmax[784];
    __shared__ int   sCnt[4];

    if (tid < 4) sCnt[tid] = 0;

    // P0: adaptive 2x2 pooling of H (centers) and F (centers_feature)
    if (tid < 192) {
        int arr = tid / 96, idx = tid - arr * 96;
        int c2 = idx >> 2, pos = idx & 3;
        const float* src = (arr == 0 ? Hw : Fw)
                           + c2 * 784 + (pos >> 1) * 14 * 28 + (pos & 1) * 14;
        float s = 0.0f;
        #pragma unroll 2
        for (int r = 0; r < 14; r++)
            for (int c = 0; c < 14; c++) s += src[r * 28 + c];
        float v = s * (1.0f / 196.0f);
        if (arr == 0) sPoolH[idx] = v; else sPoolF[idx] = v;
    }
    __syncthreads();

    // P1: centers1 = conv1x1(pooled H, Wc, bc), then flat [m*24+ch] view.
    // c1_flat[t] = chw[t/4][t%4]
    if (tid < 96) {
        int o = tid >> 2, pos = tid & 3;
        float a = bc[o];
        #pragma unroll
        for (int k = 0; k < 24; k++)
            a = fmaf(Wc[o * 24 + k], sPoolH[k * 4 + pos], a);
        sC1[tid] = a;
    }
    __syncthreads();

    // P2: sim0[m][n] = softmax_m( c1[m] . value_t[n] )
    for (int n = tid; n < 784; n += 256) {
        const float4* vp = (const float4*)(Vw + n * 24);
        float v[24];
        #pragma unroll
        for (int q = 0; q < 6; q++) {
            float4 t = vp[q];
            v[q*4] = t.x; v[q*4+1] = t.y; v[q*4+2] = t.z; v[q*4+3] = t.w;
        }
        float d[4];
        #pragma unroll
        for (int m = 0; m < 4; m++) {
            float a = 0.0f;
            #pragma unroll
            for (int k = 0; k < 24; k++) a = fmaf(sC1[m * 24 + k], v[k], a);
            d[m] = a;
        }
        float mx = fmaxf(fmaxf(d[0], d[1]), fmaxf(d[2], d[3]));
        float e0 = expf(d[0]-mx), e1 = expf(d[1]-mx),
              e2 = expf(d[2]-mx), e3 = expf(d[3]-mx);
        float inv = 1.0f / (e0 + e1 + e2 + e3);
        sSim0[0][n] = e0 * inv; sSim0[1][n] = e1 * inv;
        sSim0[2][n] = e2 * inv; sSim0[3][n] = e3 * inv;
    }
    __syncthreads();

    // P3: centers2[m][ch] = sum_n sim0[m][n] * feature_t[n][ch]
    if (tid < 192) {
        int out = tid >> 1, half = tid & 1;
        int m = out / 24, ch = out - m * 24;
        float a = 0.0f;
        int n0 = half * 392;
        for (int n = n0; n < n0 + 392; n++)
            a = fmaf(sSim0[m][n], Fw[n * 24 + ch], a);
        sPart[out][half] = a;
    }
    __syncthreads();
    if (tid < 96) sC2[tid] = sPart[tid][0] + sPart[tid][1];
    __syncthreads();

    // P4: cn[m'][c2] = centers2_flat[c2*4 + m'], L2-normalized over c2
    if (tid < 4) {
        float s = 0.0f;
        #pragma unroll
        for (int c2 = 0; c2 < 24; c2++) {
            float v = sC2[c2 * 4 + tid]; s += v * v;
        }
        sNorm[tid] = fmaxf(sqrtf(s), 1e-12f);
    }
    __syncthreads();
    if (tid < 96) {
        int m = tid / 24, c2 = tid - m * 24;
        sCN[m][c2] = sC2[c2 * 4 + m] / sNorm[m];
    }
    __syncthreads();

    // P5: per-token cosine sim -> sigmoid -> argmax (first max, like jnp)
    const float alpha = *alphap, beta = *betap;
    for (int n = tid; n < 784; n += 256) {
        float h[24]; float ns = 0.0f;
        #pragma unroll
        for (int c2 = 0; c2 < 24; c2++) {
            float v = Hw[c2 * 784 + n]; h[c2] = v; ns = fmaf(v, v, ns);
        }
        float inv = 1.0f / fmaxf(sqrtf(ns), 1e-12f);
        float best = -1.0f; int bi = 0;
        #pragma unroll
        for (int m = 0; m < 4; m++) {
            float a = 0.0f;
            #pragma unroll
            for (int c2 = 0; c2 < 24; c2++) a = fmaf(sCN[m][c2], h[c2], a);
            float z  = beta + alpha * (a * inv);
            float sg = 1.0f / (1.0f + expf(-z));
            if (sg > best) { best = sg; bi = m; }
        }
        sSimVal[n] = best; sAmax[n] = bi;
        atomicAdd(&sCnt[bi], 1);
    }
    __syncthreads();

    // P6: out_c[m][ch] = (sum_{n: amax==m} simval[n]*feature_t[n][ch] + cf) / (cnt+1)
    if (tid < 192) {
        int out = tid >> 1, half = tid & 1;
        int m = out / 24, ch = out - m * 24;
        float a = 0.0f;
        int n0 = half * 392;
        for (int n = n0; n < n0 + 392; n++)
            if (sAmax[n] == m) a = fmaf(sSimVal[n], Fw[n * 24 + ch], a);
        sPart[out][half] = a;
    }
    __syncthreads();
    if (tid < 96) {
        int m = tid / 24;
        // cf[m][ch] = pooledF flat reinterpret at t=m*24+ch -> chw[t/4][t%4] = sPoolF[t]
        sOutC[tid] = (sPart[tid][0] + sPart[tid][1] + sPoolF[tid])
                     / ((float)sCnt[m] + 1.0f);
    }
    __syncthreads();

    // P7: tokens back to windowed layout: flat g -> token n=g/24, ch=g%24
    for (int g = tid; g < CHUNK; g += 256) {
        int n = g / 24;
        int ch = g - n * 24;
        Ow[g] = sOutC[sAmax[n] * 24 + ch] * sSimVal[n];
    }
}

// ---------------------------------------------------------------------------
extern "C" void kernel_launch(void* const* d_in, const int* in_sizes, int n_in,
                              void* d_out, int out_size)
{
    const float* x  = (const float*)d_in[0];
    const float* Wv = (const float*)d_in[1];
    const float* bv = (const float*)d_in[2];
    const float* Wf = (const float*)d_in[3];
    const float* bf = (const float*)d_in[4];
    const float* W1 = (const float*)d_in[5];
    const float* b1 = (const float*)d_in[6];
    const float* Wc = (const float*)d_in[7];
    const float* bc = (const float*)d_in[8];
    const float* W2 = (const float*)d_in[9];
    const float* b2 = (const float*)d_in[10];
    const float* sa = (const float*)d_in[11];
    const float* sb = (const float*)d_in[12];
    float* out = (float*)d_out;

    float *V, *F, *H, *O;
    cudaGetSymbolAddress((void**)&V, g_V);
    cudaGetSymbolAddress((void**)&F, g_F);
    cudaGetSymbolAddress((void**)&H, g_H);
    cudaGetSymbolAddress((void**)&O, g_O);

    const size_t smem = (96 * 128 + 96 * 100) * sizeof(float);
    cudaFuncSetAttribute(conv_gemm, cudaFuncAttributeMaxDynamicSharedMemorySize,
                         (int)smem);

    dim3 grid(25, 32);
    conv_gemm<<<grid, 256, smem>>>(x, Wv, bv, V);
    conv_gemm<<<grid, 256, smem>>>(x, Wf, bf, F);
    conv_gemm<<<grid, 256, smem>>>(x, W1, b1, H);
    cluster_kernel<<<512, 256>>>(V, F, H, Wc, bc, sa, sb, O);
    conv_gemm<<<grid, 256, smem>>>(O, W2, b2, out);
}

// round 2
// speedup vs baseline: 1.1617x; 1.1617x over previous
#include <cuda_runtime.h>
#include <math.h>

#define NTOT 9633792            // 32*96*3136
#define BATCH_STRIDE 301056     // 96*3136
#define CHUNK 18816             // 24*784 per cluster-batch (512 chunks)

__device__ float g_V[NTOT];
__device__ float g_F[NTOT];
__device__ float g_H[NTOT];
__device__ float g_O[NTOT];

using u64 = unsigned long long;

__device__ __forceinline__ u64 ffma2(u64 a, u64 b, u64 c) {
    u64 d;
    asm("fma.rn.f32x2 %0, %1, %2, %3;" : "=l"(d) : "l"(a), "l"(b), "l"(c));
    return d;
}
__device__ __forceinline__ u64 dup2(float x) {
    u64 d;
    asm("mov.b64 %0, {%1, %1};" : "=l"(d) : "f"(x));
    return d;
}
__device__ __forceinline__ float2 unpk(u64 d) {
    float2 r;
    asm("mov.b64 {%0, %1}, %2;" : "=f"(r.x), "=f"(r.y) : "l"(d));
    return r;
}

// ---------------------------------------------------------------------------
// conv1x1 as GEMM with packed f32x2 FMA.
// Block: 96 co x 128 s, one batch. 256 threads: each 12 co (6 pairs) x 4 s.
// Weights k-major in smem so a co-pair is one 64-bit load.
// ---------------------------------------------------------------------------
__global__ void __launch_bounds__(256, 2) conv_gemm(
    const float* __restrict__ X, const float* __restrict__ W,
    const float* __restrict__ bias, float* __restrict__ Y)
{
    extern __shared__ float sm[];
    float* Xs = sm;              // [96][128]
    float* Ws = sm + 96 * 128;   // [96][100] k-major, padded

    const int b   = blockIdx.y;
    const int s0  = blockIdx.x * 128;
    const int tid = threadIdx.x;

    for (int i = tid; i < 96 * 96; i += 256) {
        int o = i / 96, k = i - o * 96;
        Ws[k * 100 + o] = W[i];
    }
    const float* Xb = X + (size_t)b * BATCH_STRIDE;
    for (int i = tid; i < 96 * 32; i += 256) {       // float4 staging
        int k = i >> 5, j4 = i & 31;
        int s = s0 + j4 * 4;
        float4 v = (s < 3136) ? *(const float4*)&Xb[k * 3136 + s]
                              : make_float4(0.f, 0.f, 0.f, 0.f);
        *(float4*)&Xs[k * 128 + j4 * 4] = v;
    }
    __syncthreads();

    const int j0  = (tid & 31) * 4;
    const int co0 = (tid >> 5) * 12;

    u64 acc[6][4];
    #pragma unroll
    for (int p = 0; p < 6; p++)
        #pragma unroll
        for (int j = 0; j < 4; j++) acc[p][j] = 0ull;

    #pragma unroll 4
    for (int k = 0; k < 96; k++) {
        float4 xv = *(const float4*)&Xs[k * 128 + j0];
        const u64* wp = (const u64*)&Ws[k * 100 + co0];   // 6 co-pairs
        u64 w0 = wp[0], w1 = wp[1], w2 = wp[2],
            w3 = wp[3], w4 = wp[4], w5 = wp[5];
        u64 xd[4] = {dup2(xv.x), dup2(xv.y), dup2(xv.z), dup2(xv.w)};
        #pragma unroll
        for (int j = 0; j < 4; j++) {
            acc[0][j] = ffma2(w0, xd[j], acc[0][j]);
            acc[1][j] = ffma2(w1, xd[j], acc[1][j]);
            acc[2][j] = ffma2(w2, xd[j], acc[2][j]);
            acc[3][j] = ffma2(w3, xd[j], acc[3][j]);
            acc[4][j] = ffma2(w4, xd[j], acc[4][j]);
            acc[5][j] = ffma2(w5, xd[j], acc[5][j]);
        }
    }

    if (s0 + j0 < 3136) {
        float* Yb = Y + (size_t)b * BATCH_STRIDE + s0 + j0;
        #pragma unroll
        for (int p = 0; p < 6; p++) {
            int co = co0 + 2 * p;
            float b0 = bias[co], b1 = bias[co + 1];
            float2 u0 = unpk(acc[p][0]), u1 = unpk(acc[p][1]),
                   u2 = unpk(acc[p][2]), u3 = unpk(acc[p][3]);
            *(float4*)&Yb[(size_t)co * 3136] =
                make_float4(u0.x + b0, u1.x + b0, u2.x + b0, u3.x + b0);
            *(float4*)&Yb[(size_t)(co + 1) * 3136] =
                make_float4(u0.y + b1, u1.y + b1, u2.y + b1, u3.y + b1);
        }
    }
}

// ---------------------------------------------------------------------------
// Clustering kernel v2: 512 threads/block, F+H staged in smem.
// ---------------------------------------------------------------------------
__global__ void __launch_bounds__(512) cluster_kernel(
    const float* __restrict__ Vg, const float* __restrict__ Fg,
    const float* __restrict__ Hg,
    const float* __restrict__ Wc, const float* __restrict__ bc,
    const float* __restrict__ alphap, const float* __restrict__ betap,
    float* __restrict__ Og)
{
    extern __shared__ float sm2[];
    float* sF      = sm2;                 // 18816
    float* sH      = sm2 + 18816;         // 18816
    float* sSim0   = sm2 + 37632;         // 4*784
    float* sSimVal = sSim0 + 3136;        // 784
    int*   sAmax   = (int*)(sSimVal + 784); // 784

    __shared__ float sPoolH[96], sPoolF[96], sC1[96], sC2[96], sOutC[96];
    __shared__ float sPoolPart[192][2];
    __shared__ float sP3[16][24];
    __shared__ float sCN[4][24];
    __shared__ float sNorm[4];
    __shared__ int   sCnt[4];

    const int B    = blockIdx.x;
    const int tid  = threadIdx.x;
    const int lane = tid & 31;
    const int wid  = tid >> 5;
    const float* Vw = Vg + (size_t)B * CHUNK;
    const float* Fw = Fg + (size_t)B * CHUNK;
    const float* Hw = Hg + (size_t)B * CHUNK;
    float*       Ow = Og + (size_t)B * CHUNK;

    if (tid < 4) sCnt[tid] = 0;

    // stage F and H (coalesced float4)
    {
        const float4* f4 = (const float4*)Fw;
        const float4* h4 = (const float4*)Hw;
        float4* sF4 = (float4*)sF;
        float4* sH4 = (float4*)sH;
        for (int i = tid; i < 4704; i += 512) { sF4[i] = f4[i]; sH4[i] = h4[i]; }
    }
    __syncthreads();

    // P0: adaptive 2x2 pooling (from smem), split 2 ways per unit
    if (tid < 384) {
        int u = tid >> 1, half = tid & 1;
        int arr = (u >= 96);
        int idx = arr ? u - 96 : u;
        int c2 = idx >> 2, pos = idx & 3;
        const float* src = (arr ? sF : sH)
                           + c2 * 784 + (pos >> 1) * 14 * 28 + (pos & 1) * 14
                           + half * 7 * 28;
        float s = 0.0f;
        for (int r = 0; r < 7; r++)
            #pragma unroll
            for (int c = 0; c < 14; c++) s += src[r * 28 + c];
        sPoolPart[u][half] = s;
    }
    __syncthreads();
    if (tid < 192) {
        int arr = (tid >= 96);
        int idx = arr ? tid - 96 : tid;
        float v = (sPoolPart[tid][0] + sPoolPart[tid][1]) * (1.0f / 196.0f);
        if (arr) sPoolF[idx] = v; else sPoolH[idx] = v;
    }
    __syncthreads();

    // P1: centers1 = conv1x1(pooled H, Wc, bc), flat [m*24+ch]
    if (tid < 96) {
        int o = tid >> 2, pos = tid & 3;
        float a = bc[o];
        #pragma unroll
        for (int k = 0; k < 24; k++)
            a = fmaf(Wc[o * 24 + k], sPoolH[k * 4 + pos], a);
        sC1[tid] = a;
    }
    __syncthreads();

    // P2: sim0[m][n] = softmax_m( c1[m] . value_t[n] ), V from gmem
    for (int n = tid; n < 784; n += 512) {
        const float4* vp = (const float4*)(Vw + n * 24);
        float v[24];
        #pragma unroll
        for (int q = 0; q < 6; q++) {
            float4 t = vp[q];
            v[q*4] = t.x; v[q*4+1] = t.y; v[q*4+2] = t.z; v[q*4+3] = t.w;
        }
        float d[4];
        #pragma unroll
        for (int m = 0; m < 4; m++) {
            float a = 0.0f;
            #pragma unroll
            for (int k = 0; k < 24; k++) a = fmaf(sC1[m * 24 + k], v[k], a);
            d[m] = a;
        }
        float mx = fmaxf(fmaxf(d[0], d[1]), fmaxf(d[2], d[3]));
        float e0 = expf(d[0]-mx), e1 = expf(d[1]-mx),
              e2 = expf(d[2]-mx), e3 = expf(d[3]-mx);
        float inv = 1.0f / (e0 + e1 + e2 + e3);
        sSim0[0*784+n] = e0 * inv; sSim0[1*784+n] = e1 * inv;
        sSim0[2*784+n] = e2 * inv; sSim0[3*784+n] = e3 * inv;
    }
    __syncthreads();

    // P3: centers2[m][ch] = sum_n sim0[m][n]*F[n][ch]; warp = (m, seg)
    {
        int m = wid & 3, seg = wid >> 2;
        if (lane < 24) {
            float a = 0.0f;
            int n0 = seg * 196;
            for (int n = n0; n < n0 + 196; n++)
                a = fmaf(sSim0[m * 784 + n], sF[n * 24 + lane], a);
            sP3[wid][lane] = a;
        }
    }
    __syncthreads();
    if (tid < 96) {
        int m = tid / 24, ch = tid - m * 24;
        sC2[tid] = sP3[0*4+m][ch] + sP3[1*4+m][ch]
                 + sP3[2*4+m][ch] + sP3[3*4+m][ch];
    }
    __syncthreads();

    // P4: cn[m'][c2] = centers2_flat[c2*4+m'], L2-normalized over c2
    if (tid < 4) {
        float s = 0.0f;
        #pragma unroll
        for (int c2 = 0; c2 < 24; c2++) {
            float v = sC2[c2 * 4 + tid]; s += v * v;
        }
        sNorm[tid] = fmaxf(sqrtf(s), 1e-12f);
    }
    __syncthreads();
    if (tid < 96) {
        int m = tid / 24, c2 = tid - m * 24;
        sCN[m][c2] = sC2[c2 * 4 + m] / sNorm[m];
    }
    __syncthreads();

    // P5: per-token cosine -> sigmoid -> first-argmax; counts via ballot
    const float alpha = *alphap, beta = *betap;
    for (int it = 0; it < 2; it++) {
        int n = tid + it * 512;
        bool act = (n < 784);
        int bi = -1;
        if (act) {
            float h[24]; float ns = 0.0f;
            #pragma unroll
            for (int c2 = 0; c2 < 24; c2++) {
                float v = sH[c2 * 784 + n]; h[c2] = v; ns = fmaf(v, v, ns);
            }
            float inv = 1.0f / fmaxf(sqrtf(ns), 1e-12f);
            float best = -1.0f; bi = 0;
            #pragma unroll
            for (int m = 0; m < 4; m++) {
                float a = 0.0f;
                #pragma unroll
                for (int c2 = 0; c2 < 24; c2++)
                    a = fmaf(sCN[m][c2], h[c2], a);
                float z  = beta + alpha * (a * inv);
                float sg = 1.0f / (1.0f + expf(-z));
                if (sg > best) { best = sg; bi = m; }
            }
            sSimVal[n] = best; sAmax[n] = bi;
        }
        #pragma unroll
        for (int m = 0; m < 4; m++) {
            unsigned bm = __ballot_sync(0xffffffffu, act && (bi == m));
            if (lane == 0 && bm) atomicAdd(&sCnt[m], __popc(bm));
        }
    }
    __syncthreads();

    // P6: masked aggregation; warp = (m, seg), lane = ch
    {
        int m = wid & 3, seg = wid >> 2;
        if (lane < 24) {
            float a = 0.0f;
            int n0 = seg * 196;
            for (int n = n0; n < n0 + 196; n++) {
                if (sAmax[n] == m)
                    a = fmaf(sSimVal[n], sF[n * 24 + lane], a);
            }
            sP3[wid][lane] = a;
        }
    }
    __syncthreads();
    if (tid < 96) {
        int m = tid / 24, ch = tid - m * 24;
        float s = sP3[0*4+m][ch] + sP3[1*4+m][ch]
                + sP3[2*4+m][ch] + sP3[3*4+m][ch];
        sOutC[tid] = (s + sPoolF[tid]) / ((float)sCnt[m] + 1.0f);
    }
    __syncthreads();

    // P7: broadcast centers back to tokens, float4 stores
    {
        float4* o4 = (float4*)Ow;
        const float4* c4 = (const float4*)sOutC;
        for (int n = tid; n < 784; n += 512) {
            int a = sAmax[n];
            float sv = sSimVal[n];
            #pragma unroll
            for (int q = 0; q < 6; q++) {
                float4 t = c4[a * 6 + q];
                t.x *= sv; t.y *= sv; t.z *= sv; t.w *= sv;
                o4[n * 6 + q] = t;
            }
        }
    }
}

// ---------------------------------------------------------------------------
extern "C" void kernel_launch(void* const* d_in, const int* in_sizes, int n_in,
                              void* d_out, int out_size)
{
    const float* x  = (const float*)d_in[0];
    const float* Wv = (const float*)d_in[1];
    const float* bv = (const float*)d_in[2];
    const float* Wf = (const float*)d_in[3];
    const float* bf = (const float*)d_in[4];
    const float* W1 = (const float*)d_in[5];
    const float* b1 = (const float*)d_in[6];
    const float* Wc = (const float*)d_in[7];
    const float* bc = (const float*)d_in[8];
    const float* W2 = (const float*)d_in[9];
    const float* b2 = (const float*)d_in[10];
    const float* sa = (const float*)d_in[11];
    const float* sb = (const float*)d_in[12];
    float* out = (float*)d_out;

    float *V, *F, *H, *O;
    cudaGetSymbolAddress((void**)&V, g_V);
    cudaGetSymbolAddress((void**)&F, g_F);
    cudaGetSymbolAddress((void**)&H, g_H);
    cudaGetSymbolAddress((void**)&O, g_O);

    const size_t smem_conv = (96 * 128 + 96 * 100) * sizeof(float);
    cudaFuncSetAttribute(conv_gemm, cudaFuncAttributeMaxDynamicSharedMemorySize,
                         (int)smem_conv);
    const size_t smem_clu = (size_t)(18816 * 2 + 4 * 784 + 784 + 784) * 4;
    cudaFuncSetAttribute(cluster_kernel,
                         cudaFuncAttributeMaxDynamicSharedMemorySize,
                         (int)smem_clu);

    dim3 grid(25, 32);
    conv_gemm<<<grid, 256, smem_conv>>>(x, Wv, bv, V);
    conv_gemm<<<grid, 256, smem_conv>>>(x, Wf, bf, F);
    conv_gemm<<<grid, 256, smem_conv>>>(x, W1, b1, H);
    cluster_kernel<<<512, 512, smem_clu>>>(V, F, H, Wc, bc, sa, sb, O);
    conv_gemm<<<grid, 256, smem_conv>>>(O, W2, b2, out);
}